// round 16
// baseline (speedup 1.0000x reference)
#include <cuda_runtime.h>
#include <cuda_fp16.h>
#include <math.h>
#include <stdint.h>

// Problem constants (fixed by the reference)
#define BB 64
#define TT 512
#define FF 513
#define HH 50
#define G4 200          // 4*H
#define MROWS (BB*TT)   // 32768

#define KP1 544         // K=513 padded to 17*32
#define NKC1 17
#define KP2 64          // K=50 padded to 2*32
#define NKC2 2
#define NP1 256         // W_ih rows padded
#define NP2 512         // W_out rows 0..511 (col 512 fused into GEMM2)
#define XGS 256         // xg row stride (padded)

// Scratch (static device globals — no allocation in kernel_launch)
__device__ float g_xg[MROWS * XGS];
__device__ __half g_x16[MROWS * KP1];
__device__ __half g_wih16[NP1 * KP1];
__device__ __half g_hs16[MROWS * KP2];
__device__ __half g_wo16[NP2 * KP2];

// ===========================================================================
// PTX helpers
// ===========================================================================
__device__ __forceinline__ uint32_t smem_u32(const void* p) {
    uint32_t a;
    asm("{ .reg .u64 t; cvta.to.shared.u64 t, %1; cvt.u32.u64 %0, t; }"
        : "=r"(a) : "l"(p));
    return a;
}
__device__ __forceinline__ void ldsm4(uint32_t* r, uint32_t a) {
    asm volatile("ldmatrix.sync.aligned.m8n8.x4.shared.b16 {%0,%1,%2,%3}, [%4];"
                 : "=r"(r[0]), "=r"(r[1]), "=r"(r[2]), "=r"(r[3]) : "r"(a));
}
__device__ __forceinline__ void mma16816h(float* c, const uint32_t* a,
                                          const uint32_t* b) {
    asm volatile(
        "mma.sync.aligned.m16n8k16.row.col.f32.f16.f16.f32 "
        "{%0,%1,%2,%3}, {%4,%5,%6,%7}, {%8,%9}, {%0,%1,%2,%3};"
        : "+f"(c[0]), "+f"(c[1]), "+f"(c[2]), "+f"(c[3])
        : "r"(a[0]), "r"(a[1]), "r"(a[2]), "r"(a[3]), "r"(b[0]), "r"(b[1]));
}
__device__ __forceinline__ void cpasync16(uint32_t dst, const void* src) {
    asm volatile("cp.async.cg.shared.global [%0], [%1], 16;"
                 :: "r"(dst), "l"(src));
}
#define CP_COMMIT() asm volatile("cp.async.commit_group;" ::: "memory")
#define CP_WAIT0()  asm volatile("cp.async.wait_group 0;" ::: "memory")

// fast activations: single MUFU.EX2-based, clamped; rel err ~1e-6
__device__ __forceinline__ float sigm_fast(float x) {
    x = fminf(fmaxf(x, -30.f), 30.f);
    return __fdividef(1.f, 1.f + __expf(-x));
}
__device__ __forceinline__ float tanh_fast(float x) {
    x = fminf(fmaxf(x, -15.f), 15.f);
    float e = __expf(-2.f * x);
    return __fdividef(1.f - e, 1.f + e);
}

// ===========================================================================
// Conversion kernels: fp32 -> zero-padded fp16 (x, W_ih, W_out), merged grid.
// ===========================================================================
#define NB_X   (MROWS * (KP1/8) / 256)              // 8704
#define NB_WIH ((NP1 * (KP1/8) + 255) / 256)        // 68
#define NB_WO  ((NP2 * (KP2/8) + 255) / 256)        // 16

__device__ __forceinline__ void conv_body_h(
    const float* __restrict__ src, __half* __restrict__ dst,
    int srcR, int srcC, int dstR, int dstC, int idx)
{
    int gpr = dstC >> 3;
    if (idx >= dstR * gpr) return;
    int r = idx / gpr;
    int c0 = (idx - r * gpr) * 8;
    __half hv[8];
#pragma unroll
    for (int i = 0; i < 8; ++i) {
        int c = c0 + i;
        float v = (r < srcR && c < srcC) ? __ldg(&src[(size_t)r * srcC + c]) : 0.f;
        hv[i] = __float2half_rn(v);
    }
    *(uint4*)&dst[(size_t)r * dstC + c0] = *(uint4*)hv;
}

__global__ void conv_all(const float* __restrict__ x,
                         const float* __restrict__ wih,
                         const float* __restrict__ wo)
{
    int gb = blockIdx.x;
    if (gb < NB_X)
        conv_body_h(x, g_x16, MROWS, FF, MROWS, KP1, gb * 256 + threadIdx.x);
    else if (gb < NB_X + NB_WIH)
        conv_body_h(wih, g_wih16, G4, FF, NP1, KP1,
                    (gb - NB_X) * 256 + threadIdx.x);
    else
        conv_body_h(wo, g_wo16, FF, HH, NP2, KP2,
                    (gb - NB_X - NB_WIH) * 256 + threadIdx.x);
}

// ===========================================================================
// Pure fp16 NT GEMM with bias. Single-product fp16 MMA, KC=32,
// cp.async double-buffered. 8 warps 2(m)x4(n). 2 CTAs/SM.
// nfast: if nonzero, n0 comes from blockIdx.x (adjacent blocks share A -> L2).
// w512: if non-null and blockIdx.y==0, fused col-512 GEMV epilogue
//       (requires nKC==2 so both A stages hold the full K in smem).
// ===========================================================================
#define LDR80 80
#define ABF_BYTES 10240                  // 128 rows x 80 B (fp16 tile)
#define STAGE2 (2 * ABF_BYTES)           // A | B = 20480
#define SMEM2_BIAS (2 * STAGE2)          // 40960
#define SMEM2_W512 (SMEM2_BIAS + 512)    // 41472
#define SMEM2_SZ (SMEM2_W512 + 256)      // 41728

__global__ __launch_bounds__(256, 2) void gemm_fp16_nt(
    const __half* __restrict__ Am, const __half* __restrict__ Bm,
    const float* __restrict__ bias, float* __restrict__ C,
    int ldc, int Nreal, int Kp, int nKC, int nfast,
    const float* __restrict__ w512, const float* __restrict__ b512)
{
    extern __shared__ __align__(16) char smem[];
    const uint32_t sbase = smem_u32(smem);
    float* bias_s = (float*)(smem + SMEM2_BIAS);
    float* w512_s = (float*)(smem + SMEM2_W512);

    const int tid  = threadIdx.x;
    const int lane = tid & 31;
    const int wid  = tid >> 5;
    const int wm   = wid & 1;
    const int wn   = wid >> 1;

    const int m0 = (nfast ? blockIdx.y : blockIdx.x) * 128;
    const int n0 = (nfast ? blockIdx.x : blockIdx.y) * 128;

    const bool do512 = (w512 != nullptr) && (blockIdx.y == 0);

    bool nj_act[4], jj_act[2];
#pragma unroll
    for (int nj = 0; nj < 4; ++nj)
        nj_act[nj] = (n0 + wn * 32 + nj * 8) < Nreal;
    jj_act[0] = nj_act[0] | nj_act[1];
    jj_act[1] = nj_act[2] | nj_act[3];
    const bool warp_act = jj_act[0] | jj_act[1];

    float acc[4][4][4];
#pragma unroll
    for (int i = 0; i < 4; ++i)
#pragma unroll
        for (int j = 0; j < 4; ++j)
#pragma unroll
            for (int q = 0; q < 4; ++q) acc[i][j][q] = 0.f;

    auto issue = [&](int kc, int stage) {
        const uint32_t s32 = sbase + stage * STAGE2;
#pragma unroll
        for (int i = 0; i < 2; ++i) {
            const int chunk = tid + i * 256;
            const int row = chunk >> 2;
            const int g = chunk & 3;
            const uint32_t dofs = row * LDR80 + g * 16;
            const size_t aofs = (size_t)(m0 + row) * Kp + kc * 32 + g * 8;
            const size_t bofs = (size_t)(n0 + row) * Kp + kc * 32 + g * 8;
            cpasync16(s32 + dofs, Am + aofs);
            cpasync16(s32 + ABF_BYTES + dofs, Bm + bofs);
        }
    };

    issue(0, 0);
    CP_COMMIT();
    if (tid < 128)
        bias_s[tid] = (n0 + tid < Nreal) ? bias[n0 + tid] : 0.f;
    if (do512 && tid >= 128 && tid < 128 + HH)
        w512_s[tid - 128] = w512[tid - 128];

    for (int kc = 0; kc < nKC; ++kc) {
        const int cur = kc & 1;
        CP_WAIT0();
        __syncthreads();

        if (kc + 1 < nKC) {
            issue(kc + 1, cur ^ 1);
            CP_COMMIT();
        }

        const uint32_t sA = sbase + cur * STAGE2;
        const uint32_t sB = sA + ABF_BYTES;

        if (warp_act) {
#pragma unroll
            for (int k16 = 0; k16 < 2; ++k16) {
                const uint32_t kb = k16 * 32;
                uint32_t a[4][4];
#pragma unroll
                for (int mi = 0; mi < 4; ++mi) {
                    const uint32_t off =
                        (uint32_t)(wm * 64 + mi * 16 + (lane & 15)) * LDR80 +
                        ((lane >> 4) * 16) + kb;
                    ldsm4(a[mi], sA + off);
                }
                uint32_t b[4][2];
#pragma unroll
                for (int jj = 0; jj < 2; ++jj) {
                    if (!jj_act[jj]) continue;
                    const uint32_t nrow =
                        (uint32_t)(wn * 32 + jj * 16 + ((lane >> 4) & 1) * 8 +
                                   (lane & 7));
                    const uint32_t off =
                        nrow * LDR80 + (((lane >> 3) & 1) * 16) + kb;
                    uint32_t t[4];
                    ldsm4(t, sB + off);
                    b[jj * 2][0] = t[0]; b[jj * 2][1] = t[1];
                    b[jj * 2 + 1][0] = t[2]; b[jj * 2 + 1][1] = t[3];
                }
#pragma unroll
                for (int mi = 0; mi < 4; ++mi)
#pragma unroll
                    for (int nj = 0; nj < 4; ++nj) {
                        if (!nj_act[nj]) continue;
                        mma16816h(acc[mi][nj], a[mi], b[nj]);
                    }
            }
        }
    }

    __syncthreads();

    // ---- fused col-512 GEMV: A stages 0/1 still hold K chunks 0/1 (nKC==2)
    if (do512 && tid < 128) {
        const __half* s0 = (const __half*)(smem + 0 * STAGE2 + tid * LDR80);
        const __half* s1 = (const __half*)(smem + 1 * STAGE2 + tid * LDR80);
        float s = 0.f;
#pragma unroll
        for (int k = 0; k < 32; ++k)
            s += __half2float(s0[k]) * w512_s[k];
#pragma unroll
        for (int k = 32; k < HH; ++k)
            s += __half2float(s1[k - 32]) * w512_s[k];
        C[(size_t)(m0 + tid) * ldc + 512] = s + __ldg(b512);
    }
    __syncthreads();

    // ---- slab epilogue (32-row slabs through 16 KB of smem)
    float* sC = (float*)smem;
#pragma unroll
    for (int slab = 0; slab < 4; ++slab) {
#pragma unroll
        for (int mi = 0; mi < 4; ++mi) {
            const int rl = wm * 64 + mi * 16 + (lane >> 2);
#pragma unroll
            for (int half = 0; half < 2; ++half) {
                const int rr = rl + half * 8;
                if ((rr >> 5) != slab) continue;
                const int lr = rr & 31;
                const int sw = (rr & 7) << 2;
#pragma unroll
                for (int nj = 0; nj < 4; ++nj) {
                    const int cl = wn * 32 + nj * 8 + (lane & 3) * 2;
                    const int cs = cl ^ sw;
                    sC[lr * 128 + cs]     = acc[mi][nj][half * 2];
                    sC[lr * 128 + cs + 1] = acc[mi][nj][half * 2 + 1];
                }
            }
        }
        __syncthreads();
#pragma unroll
        for (int r4 = 0; r4 < 4; ++r4) {
            const int lr = wid * 4 + r4;
            const int row = slab * 32 + lr;
            const int swr = (row & 7) << 2;
            float* dstrow = C + (size_t)(m0 + row) * ldc + n0;
#pragma unroll
            for (int q = 0; q < 4; ++q) {
                const int col = lane + q * 32;
                float v = sC[lr * 128 + (col ^ swr)] + bias_s[col];
                if (n0 + col < Nreal) dstrow[col] = v;
            }
        }
        __syncthreads();
    }
}

// ---------------------------------------------------------------------------
// LSTM scan over batch axis. One block per t (grid 512, 256 threads).
// One barrier/step, parallel per-gate activations, warp-7 fp16 store crew,
// 2-deep xg prefetch.
// ---------------------------------------------------------------------------
__global__ __launch_bounds__(256) void lstm_scan(
    const float* __restrict__ W_hh, const float* __restrict__ b_hh)
{
    __shared__ __align__(16) float h_s[2][56];

    const int t = blockIdx.x;
    const int j = threadIdx.x;
    const int lane = j & 31;
    const int wid = j >> 5;

    const int u = j >> 2;
    const int g = j & 3;
    const bool dotth = (j < 224);
    const bool actth = dotth && (g == 0) && (u < HH);
    const int row = dotth ? (g * HH + ((u < HH) ? u : HH - 1)) : 0;

    float w[HH];
    float bj = 0.f;
    if (dotth) {
#pragma unroll
        for (int k = 0; k < HH; ++k) w[k] = W_hh[row * HH + k];
        bj = b_hh[row];
    }
    float c = 0.f;
    if (j < 56) { h_s[0][j] = 0.f; h_s[1][j] = 0.f; }

    float pre0 = 0.f, pre1 = 0.f;
    if (dotth && u < HH) {
        pre0 = g_xg[(size_t)t * XGS + row];
        pre1 = g_xg[((size_t)TT + t) * XGS + row];
    }
    __syncthreads();

    for (int b = 0; b < BB; ++b) {
        const int cur = b & 1;
        if (dotth) {
            float g0 = pre0 + bj;
            pre0 = pre1;
            if (b + 2 < BB && u < HH)
                pre1 = g_xg[((size_t)(b + 2) * TT + t) * XGS + row];
            float g1 = 0.f, g2 = 0.f, g3 = 0.f;
#pragma unroll
            for (int k = 0; k < 48; k += 4) {
                float4 hv = *(const float4*)&h_s[cur][k];
                g0 += w[k + 0] * hv.x;
                g1 += w[k + 1] * hv.y;
                g2 += w[k + 2] * hv.z;
                g3 += w[k + 3] * hv.w;
            }
            g0 += w[48] * h_s[cur][48];
            g1 += w[49] * h_s[cur][49];
            float gd = (g0 + g1) + (g2 + g3);

            float act = (g == 2) ? tanh_fast(gd) : sigm_fast(gd);

            float sf = __shfl_sync(0xFFFFFFFFu, act, (lane & ~3) | 1);
            float tg = __shfl_sync(0xFFFFFFFFu, act, (lane & ~3) | 2);
            float so = __shfl_sync(0xFFFFFFFFu, act, (lane & ~3) | 3);
            if (actth) {
                c = sf * c + act * tg;
                h_s[cur ^ 1][u] = so * tanh_fast(c);
            }
        } else if (wid == 7 && b > 0) {
            const size_t o = ((size_t)(b - 1) * TT + t) * KP2;
#pragma unroll
            for (int s = 0; s < 2; ++s) {
                const int slot = lane + s * 32;
                float hv = (slot < HH) ? h_s[cur][slot] : 0.f;
                g_hs16[o + slot] = __float2half_rn(hv);
            }
        }
        __syncthreads();
    }

    if (wid == 7) {
        const size_t o = ((size_t)(BB - 1) * TT + t) * KP2;
#pragma unroll
        for (int s = 0; s < 2; ++s) {
            const int slot = lane + s * 32;
            float hv = (slot < HH) ? h_s[0][slot] : 0.f;
            g_hs16[o + slot] = __float2half_rn(hv);
        }
    }
}

// ---------------------------------------------------------------------------
extern "C" void kernel_launch(void* const* d_in, const int* in_sizes, int n_in,
                              void* d_out, int out_size)
{
    const float* x     = (const float*)d_in[0];
    const float* W_ih  = (const float*)d_in[1];
    const float* W_hh  = (const float*)d_in[2];
    const float* b_ih  = (const float*)d_in[3];
    const float* b_hh  = (const float*)d_in[4];
    const float* W_out = (const float*)d_in[5];
    const float* b_out = (const float*)d_in[6];
    float* out = (float*)d_out;

    float* xg = nullptr;
    __half *x16, *wih16, *hs16, *wo16;
    cudaGetSymbolAddress((void**)&xg, g_xg);
    cudaGetSymbolAddress((void**)&x16, g_x16);
    cudaGetSymbolAddress((void**)&wih16, g_wih16);
    cudaGetSymbolAddress((void**)&hs16, g_hs16);
    cudaGetSymbolAddress((void**)&wo16, g_wo16);

    cudaFuncSetAttribute(gemm_fp16_nt,
                         cudaFuncAttributeMaxDynamicSharedMemorySize,
                         SMEM2_SZ);

    // 0) conversions (x + weights), merged grid
    conv_all<<<NB_X + NB_WIH + NB_WO, 256>>>(x, W_ih, W_out);

    // 1) xg = x @ W_ih^T + b_ih  (pure fp16 GEMM, n-fastest for A L2 reuse)
    {
        dim3 grid(NP1 / 128, MROWS / 128);   // (2, 256), nfast=1
        gemm_fp16_nt<<<grid, 256, SMEM2_SZ>>>(x16, wih16, b_ih, xg,
                                              XGS, G4, KP1, NKC1, 1,
                                              nullptr, nullptr);
    }
    // 2) LSTM scan (writes hs as fp16)
    lstm_scan<<<TT, 256>>>(W_hh, b_hh);

    // 3) out = hs @ W_out^T + b_out, col 512 fused into blockIdx.y==0 CTAs
    {
        dim3 grid(MROWS / 128, NP2 / 128);   // (256, 4)
        gemm_fp16_nt<<<grid, 256, SMEM2_SZ>>>(hs16, wo16, b_out, out,
                                              FF, NP2, KP2, NKC2, 0,
                                              W_out + 512 * HH, b_out + 512);
    }
}

// round 17
// speedup vs baseline: 1.0014x; 1.0014x over previous
#include <cuda_runtime.h>
#include <cuda_fp16.h>
#include <math.h>
#include <stdint.h>

// Problem constants (fixed by the reference)
#define BB 64
#define TT 512
#define FF 513
#define HH 50
#define G4 200          // 4*H
#define MROWS (BB*TT)   // 32768

#define KP1 544         // K=513 padded to 17*32
#define NKC1 17
#define KP2 64          // K=50 padded to 2*32
#define NKC2 2
#define NP1 256         // W_ih rows padded
#define NP2 512         // W_out rows 0..511 (col 512 fused into GEMM2)
#define XGS 256         // xg row stride (padded)

// Scratch (static device globals — no allocation in kernel_launch)
__device__ float g_xg[MROWS * XGS];
__device__ __half g_x16[MROWS * KP1];
__device__ __half g_wih16[NP1 * KP1];
__device__ __half g_hs16[MROWS * KP2];
__device__ __half g_wo16[NP2 * KP2];

// ===========================================================================
// PTX helpers
// ===========================================================================
__device__ __forceinline__ uint32_t smem_u32(const void* p) {
    uint32_t a;
    asm("{ .reg .u64 t; cvta.to.shared.u64 t, %1; cvt.u32.u64 %0, t; }"
        : "=r"(a) : "l"(p));
    return a;
}
__device__ __forceinline__ void ldsm4(uint32_t* r, uint32_t a) {
    asm volatile("ldmatrix.sync.aligned.m8n8.x4.shared.b16 {%0,%1,%2,%3}, [%4];"
                 : "=r"(r[0]), "=r"(r[1]), "=r"(r[2]), "=r"(r[3]) : "r"(a));
}
__device__ __forceinline__ void mma16816h(float* c, const uint32_t* a,
                                          const uint32_t* b) {
    asm volatile(
        "mma.sync.aligned.m16n8k16.row.col.f32.f16.f16.f32 "
        "{%0,%1,%2,%3}, {%4,%5,%6,%7}, {%8,%9}, {%0,%1,%2,%3};"
        : "+f"(c[0]), "+f"(c[1]), "+f"(c[2]), "+f"(c[3])
        : "r"(a[0]), "r"(a[1]), "r"(a[2]), "r"(a[3]), "r"(b[0]), "r"(b[1]));
}
__device__ __forceinline__ void cpasync16(uint32_t dst, const void* src) {
    asm volatile("cp.async.cg.shared.global [%0], [%1], 16;"
                 :: "r"(dst), "l"(src));
}
#define CP_COMMIT() asm volatile("cp.async.commit_group;" ::: "memory")
#define CP_WAIT2()  asm volatile("cp.async.wait_group 2;" ::: "memory")

// fast activations: single MUFU.EX2-based, clamped; rel err ~1e-6
__device__ __forceinline__ float sigm_fast(float x) {
    x = fminf(fmaxf(x, -30.f), 30.f);
    return __fdividef(1.f, 1.f + __expf(-x));
}
__device__ __forceinline__ float tanh_fast(float x) {
    x = fminf(fmaxf(x, -15.f), 15.f);
    float e = __expf(-2.f * x);
    return __fdividef(1.f - e, 1.f + e);
}

// ===========================================================================
// Conversion kernels: fp32 -> zero-padded fp16 (x, W_ih, W_out), merged grid.
// ===========================================================================
#define NB_X   (MROWS * (KP1/8) / 256)              // 8704
#define NB_WIH ((NP1 * (KP1/8) + 255) / 256)        // 68
#define NB_WO  ((NP2 * (KP2/8) + 255) / 256)        // 16

__device__ __forceinline__ void conv_body_h(
    const float* __restrict__ src, __half* __restrict__ dst,
    int srcR, int srcC, int dstR, int dstC, int idx)
{
    int gpr = dstC >> 3;
    if (idx >= dstR * gpr) return;
    int r = idx / gpr;
    int c0 = (idx - r * gpr) * 8;
    __half hv[8];
#pragma unroll
    for (int i = 0; i < 8; ++i) {
        int c = c0 + i;
        float v = (r < srcR && c < srcC) ? __ldg(&src[(size_t)r * srcC + c]) : 0.f;
        hv[i] = __float2half_rn(v);
    }
    *(uint4*)&dst[(size_t)r * dstC + c0] = *(uint4*)hv;
}

__global__ void conv_all(const float* __restrict__ x,
                         const float* __restrict__ wih,
                         const float* __restrict__ wo)
{
    int gb = blockIdx.x;
    if (gb < NB_X)
        conv_body_h(x, g_x16, MROWS, FF, MROWS, KP1, gb * 256 + threadIdx.x);
    else if (gb < NB_X + NB_WIH)
        conv_body_h(wih, g_wih16, G4, FF, NP1, KP1,
                    (gb - NB_X) * 256 + threadIdx.x);
    else
        conv_body_h(wo, g_wo16, FF, HH, NP2, KP2,
                    (gb - NB_X - NB_WIH) * 256 + threadIdx.x);
}

// ===========================================================================
// Pure fp16 NT GEMM with bias. Single-product fp16 MMA, KC=32,
// 4-STAGE cp.async pipeline (3 chunks in flight, wait_group 2).
// 8 warps 2(m)x4(n). 2 CTAs/SM (4x20KB stages = 80KB).
// nfast: n0 from blockIdx.x (adjacent blocks share A -> L2).
// w512: if non-null and blockIdx.y==0, fused col-512 GEMV epilogue
//       (requires nKC==2 so stages 0/1 hold the full K in smem).
// ===========================================================================
#define LDR80 80
#define ABF_BYTES 10240                  // 128 rows x 80 B (fp16 tile)
#define STAGE2 (2 * ABF_BYTES)           // A | B = 20480
#define NSTG 4
#define SMEM2_BIAS (NSTG * STAGE2)       // 81920
#define SMEM2_W512 (SMEM2_BIAS + 512)    // 82432
#define SMEM2_SZ (SMEM2_W512 + 256)      // 82688

__global__ __launch_bounds__(256, 2) void gemm_fp16_nt(
    const __half* __restrict__ Am, const __half* __restrict__ Bm,
    const float* __restrict__ bias, float* __restrict__ C,
    int ldc, int Nreal, int Kp, int nKC, int nfast,
    const float* __restrict__ w512, const float* __restrict__ b512)
{
    extern __shared__ __align__(16) char smem[];
    const uint32_t sbase = smem_u32(smem);
    float* bias_s = (float*)(smem + SMEM2_BIAS);
    float* w512_s = (float*)(smem + SMEM2_W512);

    const int tid  = threadIdx.x;
    const int lane = tid & 31;
    const int wid  = tid >> 5;
    const int wm   = wid & 1;
    const int wn   = wid >> 1;

    const int m0 = (nfast ? blockIdx.y : blockIdx.x) * 128;
    const int n0 = (nfast ? blockIdx.x : blockIdx.y) * 128;

    const bool do512 = (w512 != nullptr) && (blockIdx.y == 0);

    bool nj_act[4], jj_act[2];
#pragma unroll
    for (int nj = 0; nj < 4; ++nj)
        nj_act[nj] = (n0 + wn * 32 + nj * 8) < Nreal;
    jj_act[0] = nj_act[0] | nj_act[1];
    jj_act[1] = nj_act[2] | nj_act[3];
    const bool warp_act = jj_act[0] | jj_act[1];

    float acc[4][4][4];
#pragma unroll
    for (int i = 0; i < 4; ++i)
#pragma unroll
        for (int j = 0; j < 4; ++j)
#pragma unroll
            for (int q = 0; q < 4; ++q) acc[i][j][q] = 0.f;

    auto issue = [&](int kc, int stage) {
        const uint32_t s32 = sbase + stage * STAGE2;
#pragma unroll
        for (int i = 0; i < 2; ++i) {
            const int chunk = tid + i * 256;
            const int row = chunk >> 2;
            const int g = chunk & 3;
            const uint32_t dofs = row * LDR80 + g * 16;
            const size_t aofs = (size_t)(m0 + row) * Kp + kc * 32 + g * 8;
            const size_t bofs = (size_t)(n0 + row) * Kp + kc * 32 + g * 8;
            cpasync16(s32 + dofs, Am + aofs);
            cpasync16(s32 + ABF_BYTES + dofs, Bm + bofs);
        }
    };

    // prologue: fill up to 3 stages (constant commit depth)
#pragma unroll
    for (int i = 0; i < 3; ++i) {
        if (i < nKC) issue(i, i);
        CP_COMMIT();
    }
    if (tid < 128)
        bias_s[tid] = (n0 + tid < Nreal) ? bias[n0 + tid] : 0.f;
    if (do512 && tid >= 128 && tid < 128 + HH)
        w512_s[tid - 128] = w512[tid - 128];

    for (int kc = 0; kc < nKC; ++kc) {
        const int cur = kc & (NSTG - 1);
        CP_WAIT2();        // chunk kc's group complete (3 groups in flight max)
        __syncthreads();   // all warps past compute of kc-1 (stage reuse safe)

        if (kc + 3 < nKC) issue(kc + 3, (kc + 3) & (NSTG - 1));
        CP_COMMIT();       // keep group count constant (empty ok)

        const uint32_t sA = sbase + cur * STAGE2;
        const uint32_t sB = sA + ABF_BYTES;

        if (warp_act) {
#pragma unroll
            for (int k16 = 0; k16 < 2; ++k16) {
                const uint32_t kb = k16 * 32;
                uint32_t a[4][4];
#pragma unroll
                for (int mi = 0; mi < 4; ++mi) {
                    const uint32_t off =
                        (uint32_t)(wm * 64 + mi * 16 + (lane & 15)) * LDR80 +
                        ((lane >> 4) * 16) + kb;
                    ldsm4(a[mi], sA + off);
                }
                uint32_t b[4][2];
#pragma unroll
                for (int jj = 0; jj < 2; ++jj) {
                    if (!jj_act[jj]) continue;
                    const uint32_t nrow =
                        (uint32_t)(wn * 32 + jj * 16 + ((lane >> 4) & 1) * 8 +
                                   (lane & 7));
                    const uint32_t off =
                        nrow * LDR80 + (((lane >> 3) & 1) * 16) + kb;
                    uint32_t t[4];
                    ldsm4(t, sB + off);
                    b[jj * 2][0] = t[0]; b[jj * 2][1] = t[1];
                    b[jj * 2 + 1][0] = t[2]; b[jj * 2 + 1][1] = t[3];
                }
#pragma unroll
                for (int mi = 0; mi < 4; ++mi)
#pragma unroll
                    for (int nj = 0; nj < 4; ++nj) {
                        if (!nj_act[nj]) continue;
                        mma16816h(acc[mi][nj], a[mi], b[nj]);
                    }
            }
        }
    }

    __syncthreads();

    // ---- fused col-512 GEMV: stages 0/1 hold K chunks 0/1 (nKC==2)
    if (do512 && tid < 128) {
        const __half* s0 = (const __half*)(smem + 0 * STAGE2 + tid * LDR80);
        const __half* s1 = (const __half*)(smem + 1 * STAGE2 + tid * LDR80);
        float s = 0.f;
#pragma unroll
        for (int k = 0; k < 32; ++k)
            s += __half2float(s0[k]) * w512_s[k];
#pragma unroll
        for (int k = 32; k < HH; ++k)
            s += __half2float(s1[k - 32]) * w512_s[k];
        C[(size_t)(m0 + tid) * ldc + 512] = s + __ldg(b512);
    }
    __syncthreads();

    // ---- slab epilogue (32-row slabs through 16 KB of smem)
    float* sC = (float*)smem;
#pragma unroll
    for (int slab = 0; slab < 4; ++slab) {
#pragma unroll
        for (int mi = 0; mi < 4; ++mi) {
            const int rl = wm * 64 + mi * 16 + (lane >> 2);
#pragma unroll
            for (int half = 0; half < 2; ++half) {
                const int rr = rl + half * 8;
                if ((rr >> 5) != slab) continue;
                const int lr = rr & 31;
                const int sw = (rr & 7) << 2;
#pragma unroll
                for (int nj = 0; nj < 4; ++nj) {
                    const int cl = wn * 32 + nj * 8 + (lane & 3) * 2;
                    const int cs = cl ^ sw;
                    sC[lr * 128 + cs]     = acc[mi][nj][half * 2];
                    sC[lr * 128 + cs + 1] = acc[mi][nj][half * 2 + 1];
                }
            }
        }
        __syncthreads();
#pragma unroll
        for (int r4 = 0; r4 < 4; ++r4) {
            const int lr = wid * 4 + r4;
            const int row = slab * 32 + lr;
            const int swr = (row & 7) << 2;
            float* dstrow = C + (size_t)(m0 + row) * ldc + n0;
#pragma unroll
            for (int q = 0; q < 4; ++q) {
                const int col = lane + q * 32;
                float v = sC[lr * 128 + (col ^ swr)] + bias_s[col];
                if (n0 + col < Nreal) dstrow[col] = v;
            }
        }
        __syncthreads();
    }
}

// ---------------------------------------------------------------------------
// LSTM scan over batch axis. One block per t (grid 512, 256 threads).
// One barrier/step, parallel per-gate activations, warp-7 fp16 store crew,
// 2-deep xg prefetch.
// ---------------------------------------------------------------------------
__global__ __launch_bounds__(256) void lstm_scan(
    const float* __restrict__ W_hh, const float* __restrict__ b_hh)
{
    __shared__ __align__(16) float h_s[2][56];

    const int t = blockIdx.x;
    const int j = threadIdx.x;
    const int lane = j & 31;
    const int wid = j >> 5;

    const int u = j >> 2;
    const int g = j & 3;
    const bool dotth = (j < 224);
    const bool actth = dotth && (g == 0) && (u < HH);
    const int row = dotth ? (g * HH + ((u < HH) ? u : HH - 1)) : 0;

    float w[HH];
    float bj = 0.f;
    if (dotth) {
#pragma unroll
        for (int k = 0; k < HH; ++k) w[k] = W_hh[row * HH + k];
        bj = b_hh[row];
    }
    float c = 0.f;
    if (j < 56) { h_s[0][j] = 0.f; h_s[1][j] = 0.f; }

    float pre0 = 0.f, pre1 = 0.f;
    if (dotth && u < HH) {
        pre0 = g_xg[(size_t)t * XGS + row];
        pre1 = g_xg[((size_t)TT + t) * XGS + row];
    }
    __syncthreads();

    for (int b = 0; b < BB; ++b) {
        const int cur = b & 1;
        if (dotth) {
            float g0 = pre0 + bj;
            pre0 = pre1;
            if (b + 2 < BB && u < HH)
                pre1 = g_xg[((size_t)(b + 2) * TT + t) * XGS + row];
            float g1 = 0.f, g2 = 0.f, g3 = 0.f;
#pragma unroll
            for (int k = 0; k < 48; k += 4) {
                float4 hv = *(const float4*)&h_s[cur][k];
                g0 += w[k + 0] * hv.x;
                g1 += w[k + 1] * hv.y;
                g2 += w[k + 2] * hv.z;
                g3 += w[k + 3] * hv.w;
            }
            g0 += w[48] * h_s[cur][48];
            g1 += w[49] * h_s[cur][49];
            float gd = (g0 + g1) + (g2 + g3);

            float act = (g == 2) ? tanh_fast(gd) : sigm_fast(gd);

            float sf = __shfl_sync(0xFFFFFFFFu, act, (lane & ~3) | 1);
            float tg = __shfl_sync(0xFFFFFFFFu, act, (lane & ~3) | 2);
            float so = __shfl_sync(0xFFFFFFFFu, act, (lane & ~3) | 3);
            if (actth) {
                c = sf * c + act * tg;
                h_s[cur ^ 1][u] = so * tanh_fast(c);
            }
        } else if (wid == 7 && b > 0) {
            const size_t o = ((size_t)(b - 1) * TT + t) * KP2;
#pragma unroll
            for (int s = 0; s < 2; ++s) {
                const int slot = lane + s * 32;
                float hv = (slot < HH) ? h_s[cur][slot] : 0.f;
                g_hs16[o + slot] = __float2half_rn(hv);
            }
        }
        __syncthreads();
    }

    if (wid == 7) {
        const size_t o = ((size_t)(BB - 1) * TT + t) * KP2;
#pragma unroll
        for (int s = 0; s < 2; ++s) {
            const int slot = lane + s * 32;
            float hv = (slot < HH) ? h_s[0][slot] : 0.f;
            g_hs16[o + slot] = __float2half_rn(hv);
        }
    }
}

// ---------------------------------------------------------------------------
extern "C" void kernel_launch(void* const* d_in, const int* in_sizes, int n_in,
                              void* d_out, int out_size)
{
    const float* x     = (const float*)d_in[0];
    const float* W_ih  = (const float*)d_in[1];
    const float* W_hh  = (const float*)d_in[2];
    const float* b_ih  = (const float*)d_in[3];
    const float* b_hh  = (const float*)d_in[4];
    const float* W_out = (const float*)d_in[5];
    const float* b_out = (const float*)d_in[6];
    float* out = (float*)d_out;

    float* xg = nullptr;
    __half *x16, *wih16, *hs16, *wo16;
    cudaGetSymbolAddress((void**)&xg, g_xg);
    cudaGetSymbolAddress((void**)&x16, g_x16);
    cudaGetSymbolAddress((void**)&wih16, g_wih16);
    cudaGetSymbolAddress((void**)&hs16, g_hs16);
    cudaGetSymbolAddress((void**)&wo16, g_wo16);

    cudaFuncSetAttribute(gemm_fp16_nt,
                         cudaFuncAttributeMaxDynamicSharedMemorySize,
                         SMEM2_SZ);

    // 0) conversions (x + weights), merged grid
    conv_all<<<NB_X + NB_WIH + NB_WO, 256>>>(x, W_ih, W_out);

    // 1) xg = x @ W_ih^T + b_ih  (pure fp16 GEMM, n-fastest for A L2 reuse)
    {
        dim3 grid(NP1 / 128, MROWS / 128);   // (2, 256), nfast=1
        gemm_fp16_nt<<<grid, 256, SMEM2_SZ>>>(x16, wih16, b_ih, xg,
                                              XGS, G4, KP1, NKC1, 1,
                                              nullptr, nullptr);
    }
    // 2) LSTM scan (writes hs as fp16)
    lstm_scan<<<TT, 256>>>(W_hh, b_hh);

    // 3) out = hs @ W_out^T + b_out, col 512 fused into blockIdx.y==0 CTAs
    {
        dim3 grid(MROWS / 128, NP2 / 128);   // (256, 4)
        gemm_fp16_nt<<<grid, 256, SMEM2_SZ>>>(hs16, wo16, b_out, out,
                                              FF, NP2, KP2, NKC2, 0,
                                              W_out + 512 * HH, b_out + 512);
    }
}